// round 13
// baseline (speedup 1.0000x reference)
#include <cuda_runtime.h>
#include <cstdint>

#define T_STEPS 256
#define BATCH   16
#define EMB     1024
#define HID     1024
#define VOCAB   32000
#define M_TOTAL (T_STEPS * BATCH)   // 4096

// Scratch (static device globals — allocation-free per harness rules)
__device__ float    g_U    [M_TOTAL * HID];   // 16 MB
__device__ float    g_Hs   [M_TOTAL * HID];   // 16 MB (fp32 hidden states)
__device__ float    g_Hs32 [M_TOTAL * HID];   // 16 MB (tf32-rounded copy)
__device__ float    g_Whq32[HID * VOCAB];     // 128 MB (tf32-rounded W_hq)
__device__ unsigned g_gen;                    // grid-barrier counter

// ===========================================================================
// helpers
// ===========================================================================
__device__ __forceinline__ float ftf32(float x) {
    unsigned u;
    asm("cvt.rna.tf32.f32 %0, %1;" : "=r"(u) : "f"(x));
    return __uint_as_float(u);
}
__device__ __forceinline__ unsigned ftf32u(float x) {
    unsigned u;
    asm("cvt.rna.tf32.f32 %0, %1;" : "=r"(u) : "f"(x));
    return u;
}
__device__ __forceinline__ uint32_t smem_u32(const void* p) {
    uint32_t a;
    asm("{ .reg .u64 t; cvta.to.shared.u64 t, %1; cvt.u32.u64 %0, t; }"
        : "=r"(a) : "l"(p));
    return a;
}
__device__ __forceinline__ void cp16(uint32_t dst, const void* src) {
    asm volatile("cp.async.cg.shared.global [%0], [%1], 16;"
                 :: "r"(dst), "l"(src) : "memory");
}
#define CP_COMMIT() asm volatile("cp.async.commit_group;" ::: "memory")
#define CP_WAIT2()  asm volatile("cp.async.wait_group 2;" ::: "memory")
#define CP_WAIT0()  asm volatile("cp.async.wait_group 0;" ::: "memory")

__device__ __forceinline__ void mma_tf32(float c[4], const unsigned a[4],
                                         const unsigned b[2]) {
    asm volatile(
        "mma.sync.aligned.m16n8k8.row.col.f32.tf32.tf32.f32 "
        "{%0,%1,%2,%3},{%4,%5,%6,%7},{%8,%9},{%0,%1,%2,%3};\n"
        : "+f"(c[0]), "+f"(c[1]), "+f"(c[2]), "+f"(c[3])
        : "r"(a[0]), "r"(a[1]), "r"(a[2]), "r"(a[3]), "r"(b[0]), "r"(b[1]));
}

// ===========================================================================
// K_round: elementwise tf32-rne rounding, 4 float4 per thread (MLP=4)
// ===========================================================================
__global__ void k_round4(const float* __restrict__ src, float* __restrict__ dst,
                         int n4) {
    int base = blockIdx.x * blockDim.x * 4 + threadIdx.x;
    float4 v[4];
    #pragma unroll
    for (int q = 0; q < 4; q++) {
        int i = base + q * blockDim.x;
        if (i < n4) v[q] = ((const float4*)src)[i];
    }
    #pragma unroll
    for (int q = 0; q < 4; q++) {
        int i = base + q * blockDim.x;
        if (i < n4) {
            float4 t = v[q];
            t.x = ftf32(t.x); t.y = ftf32(t.y); t.z = ftf32(t.z); t.w = ftf32(t.w);
            ((float4*)dst)[i] = t;
        }
    }
}

// ===========================================================================
// K1: U = gather(W_e, X) @ W_xh + b_h  via legacy mma.sync tf32
// ===========================================================================
#define AS_STRIDE 36
#define BS_STRIDE 132
#define AS_BUF (128 * AS_STRIDE)
#define BS_BUF (32 * BS_STRIDE)
#define K1_SMEM ((2 * AS_BUF + 2 * BS_BUF) * 4 + 512)

__global__ void k_embed_mma(const int* __restrict__ X,
                            const float* __restrict__ We,
                            const float* __restrict__ Wxh,
                            const float* __restrict__ bh) {
    extern __shared__ float sm[];
    float* As = sm;
    float* Bs = sm + 2 * AS_BUF;
    int*   sIdx = (int*)(sm + 2 * AS_BUF + 2 * BS_BUF);

    const int tid  = threadIdx.x;
    const int lane = tid & 31, warp = tid >> 5;
    const int gid  = lane >> 2, tig = lane & 3;
    const int wm = (warp >> 2) * 64;
    const int wn = (warp & 3) * 32;
    const int m0 = blockIdx.y * 128;
    const int n0 = blockIdx.x * 128;

    if (tid < 128) sIdx[tid] = X[m0 + tid];
    __syncthreads();

    float c[4][4][4];
    #pragma unroll
    for (int mi = 0; mi < 4; mi++)
        #pragma unroll
        for (int ni = 0; ni < 4; ni++)
            #pragma unroll
            for (int r = 0; r < 4; r++) c[mi][ni][r] = 0.f;

    float4 pa[4], pb[4];
    auto ldA = [&](int k0) {
        #pragma unroll
        for (int q = 0; q < 4; q++) {
            int id = tid + q * 256, r = id >> 3, c4 = id & 7;
            pa[q] = *(const float4*)&We[(size_t)sIdx[r] * EMB + k0 + c4 * 4];
        }
    };
    auto ldB = [&](int k0) {
        #pragma unroll
        for (int q = 0; q < 4; q++) {
            int id = tid + q * 256, r = id >> 5, c4 = id & 31;
            pb[q] = *(const float4*)&Wxh[(size_t)(k0 + r) * HID + n0 + c4 * 4];
        }
    };
    auto stA = [&](float* Ab) {
        #pragma unroll
        for (int q = 0; q < 4; q++) {
            int id = tid + q * 256, r = id >> 3, c4 = id & 7;
            float4 v = pa[q];
            v.x = ftf32(v.x); v.y = ftf32(v.y); v.z = ftf32(v.z); v.w = ftf32(v.w);
            *(float4*)&Ab[r * AS_STRIDE + c4 * 4] = v;
        }
    };
    auto stB = [&](float* Bb) {
        #pragma unroll
        for (int q = 0; q < 4; q++) {
            int id = tid + q * 256, r = id >> 5, c4 = id & 31;
            float4 v = pb[q];
            v.x = ftf32(v.x); v.y = ftf32(v.y); v.z = ftf32(v.z); v.w = ftf32(v.w);
            *(float4*)&Bb[r * BS_STRIDE + c4 * 4] = v;
        }
    };

    ldA(0); ldB(0);
    stA(As); stB(Bs);
    __syncthreads();

    int buf = 0;
    for (int kt = 0; kt < 32; kt++) {
        if (kt < 31) { ldA((kt + 1) * 32); ldB((kt + 1) * 32); }
        const float* Ab = As + buf * AS_BUF;
        const float* Bb = Bs + buf * BS_BUF;
        #pragma unroll
        for (int kk = 0; kk < 32; kk += 8) {
            unsigned af[4][4], bf[4][2];
            #pragma unroll
            for (int mi = 0; mi < 4; mi++) {
                int mr = wm + mi * 16 + gid;
                af[mi][0] = __float_as_uint(Ab[mr * AS_STRIDE + kk + tig]);
                af[mi][1] = __float_as_uint(Ab[(mr + 8) * AS_STRIDE + kk + tig]);
                af[mi][2] = __float_as_uint(Ab[mr * AS_STRIDE + kk + tig + 4]);
                af[mi][3] = __float_as_uint(Ab[(mr + 8) * AS_STRIDE + kk + tig + 4]);
            }
            #pragma unroll
            for (int ni = 0; ni < 4; ni++) {
                int nc = wn + ni * 8 + gid;
                bf[ni][0] = __float_as_uint(Bb[(kk + tig) * BS_STRIDE + nc]);
                bf[ni][1] = __float_as_uint(Bb[(kk + tig + 4) * BS_STRIDE + nc]);
            }
            #pragma unroll
            for (int mi = 0; mi < 4; mi++)
                #pragma unroll
                for (int ni = 0; ni < 4; ni++)
                    mma_tf32(c[mi][ni], af[mi], bf[ni]);
        }
        if (kt < 31) { stA(As + (buf ^ 1) * AS_BUF); stB(Bs + (buf ^ 1) * BS_BUF); }
        __syncthreads();
        buf ^= 1;
    }

    #pragma unroll
    for (int mi = 0; mi < 4; mi++) {
        int mr = m0 + wm + mi * 16 + gid;
        #pragma unroll
        for (int ni = 0; ni < 4; ni++) {
            int nc = n0 + wn + ni * 8 + tig * 2;
            float b0 = bh[nc], b1 = bh[nc + 1];
            float2 v0 = make_float2(c[mi][ni][0] + b0, c[mi][ni][1] + b1);
            float2 v1 = make_float2(c[mi][ni][2] + b0, c[mi][ni][3] + b1);
            *(float2*)&g_U[(size_t)mr * HID + nc]       = v0;
            *(float2*)&g_U[(size_t)(mr + 8) * HID + nc] = v1;
        }
    }
}

// ===========================================================================
// K2 (persistent, tensor-core recurrence) — emits fp32 h and tf32 h
// ===========================================================================
#define NCTA2 64
#define JPC2  16
#define HSTR  1028
#define RNN2_SMEM ((BATCH * HSTR + 16 * 256) * 4)

__global__ void __launch_bounds__(512, 1) k_rnn_tc(const float* __restrict__ Whh) {
    extern __shared__ float sm[];
    float* hsm = sm;
    float* red = sm + BATCH * HSTR;

    const int tid  = threadIdx.x;
    const int lane = tid & 31, warp = tid >> 5;
    const int gid  = lane >> 2, tig = lane & 3;
    const int j0   = blockIdx.x * JPC2;
    const int kw   = warp * 64;

    unsigned bf[2][8][2];
    #pragma unroll
    for (int s = 0; s < 2; s++)
        #pragma unroll
        for (int q = 0; q < 8; q++) {
            int k = kw + q * 8 + tig;
            int j = j0 + s * 8 + gid;
            bf[s][q][0] = ftf32u(Whh[(size_t)k * HID + j]);
            bf[s][q][1] = ftf32u(Whh[(size_t)(k + 4) * HID + j]);
        }

    for (int t = 0; t < T_STEPS; t++) {
        float c0[4] = {0.f, 0.f, 0.f, 0.f};
        float c1[4] = {0.f, 0.f, 0.f, 0.f};

        if (t > 0) {
            const float* hp = g_Hs + (size_t)(t - 1) * BATCH * HID;
            #pragma unroll
            for (int q = 0; q < 8; q++) {
                int f4 = tid + q * 512;
                int row = f4 >> 8, c4 = f4 & 255;
                float4 v = __ldcg((const float4*)&hp[(size_t)row * HID + c4 * 4]);
                *(float4*)&hsm[row * HSTR + c4 * 4] = v;
            }
            __syncthreads();

            #pragma unroll
            for (int q = 0; q < 8; q++) {
                const int k0 = kw + q * 8;
                unsigned af[4];
                af[0] = ftf32u(hsm[gid * HSTR + k0 + tig]);
                af[1] = ftf32u(hsm[(gid + 8) * HSTR + k0 + tig]);
                af[2] = ftf32u(hsm[gid * HSTR + k0 + tig + 4]);
                af[3] = ftf32u(hsm[(gid + 8) * HSTR + k0 + tig + 4]);
                mma_tf32(c0, af, bf[0][q]);
                mma_tf32(c1, af, bf[1][q]);
            }
        }

        {
            float* rw = red + warp * 256;
            rw[gid * 16 + tig * 2]           = c0[0];
            rw[gid * 16 + tig * 2 + 1]       = c0[1];
            rw[(gid + 8) * 16 + tig * 2]     = c0[2];
            rw[(gid + 8) * 16 + tig * 2 + 1] = c0[3];
            rw[gid * 16 + 8 + tig * 2]           = c1[0];
            rw[gid * 16 + 8 + tig * 2 + 1]       = c1[1];
            rw[(gid + 8) * 16 + 8 + tig * 2]     = c1[2];
            rw[(gid + 8) * 16 + 8 + tig * 2 + 1] = c1[3];
        }
        __syncthreads();

        if (tid < 256) {
            const int b = tid >> 4, n = tid & 15;
            float s = 0.f;
            if (t > 0) {
                #pragma unroll
                for (int w = 0; w < 16; w++)
                    s += red[w * 256 + b * 16 + n];
            }
            const size_t m = (size_t)t * BATCH + b;
            float val = tanhf(g_U[m * HID + j0 + n] + s);
            g_Hs[m * HID + j0 + n]   = val;
            g_Hs32[m * HID + j0 + n] = ftf32(val);
        }
        __threadfence();
        __syncthreads();

        if (t < T_STEPS - 1) {
            if (tid == 0) {
                atomicAdd(&g_gen, 1u);
                const unsigned target = (unsigned)NCTA2 * (t + 1);
                while (*(volatile unsigned*)&g_gen < target) __nanosleep(32);
                __threadfence();
            }
            __syncthreads();
        }
    }
}

// ===========================================================================
// K3: logits = Hs32 @ Whq32 + b_q   (legacy mma tf32, cp.async 4-stage)
//     512 threads, CTA 128x256, warp tile 64x32 (2M x 8N) -> 16 warps,
//     64 accum regs/thread, single CTA/SM but 4 warps/SMSP latency hiding
// ===========================================================================
#define BM3 128
#define BN3 256
#define BK3 16
#define A3S 20
#define B3S 264
#define A3_BYTES (BM3 * A3S * 4)
#define B3_BYTES (BK3 * B3S * 4)
#define STG3 (A3_BYTES + B3_BYTES)
#define K3_SMEM (4 * STG3)

__global__ void __launch_bounds__(512, 1)
k_out_gemm3(const float* __restrict__ bq, float* __restrict__ out) {
    extern __shared__ char smc[];
    const uint32_t sb = smem_u32(smc);

    const int tid  = threadIdx.x;
    const int lane = tid & 31, warp = tid >> 5;   // 16 warps
    const int gid  = lane >> 2, tig = lane & 3;
    const int wm = (warp & 1) * 64;       // 2 warps along M
    const int wn = (warp >> 1) * 32;      // 8 warps along N
    const int m0 = blockIdx.x * BM3;      // m fastest -> B tile L2 reuse
    const int n0 = blockIdx.y * BN3;

    auto issue = [&](int kt) {
        const int s = kt & 3;
        const uint32_t ab = sb + s * STG3;
        const uint32_t bb = ab + A3_BYTES;
        const int k0 = kt * BK3;
        {   // A: 512 16B chunks, 1 per thread
            int m = tid >> 2, kq = tid & 3;
            cp16(ab + m * (A3S * 4) + kq * 16,
                 &g_Hs32[(size_t)(m0 + m) * HID + k0 + kq * 4]);
        }
        #pragma unroll
        for (int q = 0; q < 2; q++) {     // B: 1024 16B chunks, 2 per thread
            int id = tid + q * 512;
            int k = id >> 6, n4 = id & 63;
            cp16(bb + k * (B3S * 4) + n4 * 16,
                 &g_Whq32[(size_t)(k0 + k) * VOCAB + n0 + n4 * 4]);
        }
        CP_COMMIT();
    };

    float c[4][4][4];
    #pragma unroll
    for (int mi = 0; mi < 4; mi++)
        #pragma unroll
        for (int ni = 0; ni < 4; ni++)
            #pragma unroll
            for (int r = 0; r < 4; r++) c[mi][ni][r] = 0.f;

    issue(0); issue(1); issue(2);

    for (int kt = 0; kt < 64; kt++) {
        CP_WAIT2();
        __syncthreads();
        if (kt + 3 < 64) issue(kt + 3);

        const int s = kt & 3;
        const float* As = (const float*)(smc + s * STG3);
        const float* Bs = (const float*)(smc + s * STG3 + A3_BYTES);

        #pragma unroll
        for (int kk = 0; kk < BK3; kk += 8) {
            unsigned af[4][4], bf[4][2];
            #pragma unroll
            for (int mi = 0; mi < 4; mi++) {
                int mr = wm + mi * 16 + gid;
                af[mi][0] = __float_as_uint(As[mr * A3S + kk + tig]);
                af[mi][1] = __float_as_uint(As[(mr + 8) * A3S + kk + tig]);
                af[mi][2] = __float_as_uint(As[mr * A3S + kk + tig + 4]);
                af[mi][3] = __float_as_uint(As[(mr + 8) * A3S + kk + tig + 4]);
            }
            #pragma unroll
            for (int ni = 0; ni < 4; ni++) {
                int nc = wn + ni * 8 + gid;
                bf[ni][0] = __float_as_uint(Bs[(kk + tig) * B3S + nc]);
                bf[ni][1] = __float_as_uint(Bs[(kk + tig + 4) * B3S + nc]);
            }
            #pragma unroll
            for (int mi = 0; mi < 4; mi++)
                #pragma unroll
                for (int ni = 0; ni < 4; ni++)
                    mma_tf32(c[mi][ni], af[mi], bf[ni]);
        }
    }
    CP_WAIT0();

    #pragma unroll
    for (int mi = 0; mi < 4; mi++) {
        int mr = m0 + wm + mi * 16 + gid;
        #pragma unroll
        for (int ni = 0; ni < 4; ni++) {
            int nc = n0 + wn + ni * 8 + tig * 2;
            float b0 = bq[nc], b1 = bq[nc + 1];
            float2 v0 = make_float2(c[mi][ni][0] + b0, c[mi][ni][1] + b1);
            float2 v1 = make_float2(c[mi][ni][2] + b0, c[mi][ni][3] + b1);
            *(float2*)&out[(size_t)mr * VOCAB + nc]       = v0;
            *(float2*)&out[(size_t)(mr + 8) * VOCAB + nc] = v1;
        }
    }
}

// ===========================================================================
extern "C" void kernel_launch(void* const* d_in, const int* in_sizes, int n_in,
                              void* d_out, int out_size) {
    const int*   X   = (const int*)  d_in[0];
    const float* We  = (const float*)d_in[1];
    const float* Wxh = (const float*)d_in[2];
    const float* Whh = (const float*)d_in[3];
    const float* bh  = (const float*)d_in[4];
    const float* Whq = (const float*)d_in[5];
    const float* bq  = (const float*)d_in[6];
    float*       out = (float*)d_out;

    cudaFuncSetAttribute(k_embed_mma,
                         cudaFuncAttributeMaxDynamicSharedMemorySize, K1_SMEM);
    cudaFuncSetAttribute(k_rnn_tc,
                         cudaFuncAttributeMaxDynamicSharedMemorySize, RNN2_SMEM);
    cudaFuncSetAttribute(k_out_gemm3,
                         cudaFuncAttributeMaxDynamicSharedMemorySize, K3_SMEM);

    void *gen_ptr = nullptr, *whq32 = nullptr;
    cudaGetSymbolAddress(&gen_ptr, g_gen);
    cudaGetSymbolAddress(&whq32, g_Whq32);

    cudaMemsetAsync(gen_ptr, 0, sizeof(unsigned), 0);

    {
        int n4 = HID * VOCAB / 4;
        int blocks = (n4 + 1023) / 1024;
        k_round4<<<blocks, 256>>>(Whq, (float*)whq32, n4);
    }
    k_embed_mma<<<dim3(HID / 128, M_TOTAL / 128), 256, K1_SMEM>>>(X, We, Wxh, bh);
    k_rnn_tc<<<NCTA2, 512, RNN2_SMEM>>>(Whh);
    k_out_gemm3<<<dim3(M_TOTAL / BM3, VOCAB / BN3), 512, K3_SMEM>>>(bq, out);
}

// round 14
// speedup vs baseline: 1.1096x; 1.1096x over previous
#include <cuda_runtime.h>
#include <cstdint>

#define T_STEPS 256
#define BATCH   16
#define EMB     1024
#define HID     1024
#define VOCAB   32000
#define M_TOTAL (T_STEPS * BATCH)   // 4096

// Scratch (static device globals — allocation-free per harness rules)
__device__ float    g_U    [M_TOTAL * HID];   // 16 MB
__device__ float    g_Hs   [M_TOTAL * HID];   // 16 MB (fp32 hidden states)
__device__ float    g_Hs32 [M_TOTAL * HID];   // 16 MB (tf32-rounded copy)
__device__ float    g_Whq32[HID * VOCAB];     // 128 MB (tf32-rounded W_hq)
__device__ unsigned g_gen;                    // grid-barrier counter

// ===========================================================================
// helpers
// ===========================================================================
__device__ __forceinline__ float ftf32(float x) {
    unsigned u;
    asm("cvt.rna.tf32.f32 %0, %1;" : "=r"(u) : "f"(x));
    return __uint_as_float(u);
}
__device__ __forceinline__ unsigned ftf32u(float x) {
    unsigned u;
    asm("cvt.rna.tf32.f32 %0, %1;" : "=r"(u) : "f"(x));
    return u;
}
__device__ __forceinline__ uint32_t smem_u32(const void* p) {
    uint32_t a;
    asm("{ .reg .u64 t; cvta.to.shared.u64 t, %1; cvt.u32.u64 %0, t; }"
        : "=r"(a) : "l"(p));
    return a;
}
__device__ __forceinline__ void cp16(uint32_t dst, const void* src) {
    asm volatile("cp.async.cg.shared.global [%0], [%1], 16;"
                 :: "r"(dst), "l"(src) : "memory");
}
#define CP_COMMIT() asm volatile("cp.async.commit_group;" ::: "memory")
#define CP_WAIT2()  asm volatile("cp.async.wait_group 2;" ::: "memory")
#define CP_WAIT0()  asm volatile("cp.async.wait_group 0;" ::: "memory")

__device__ __forceinline__ void mma_tf32(float c[4], const unsigned a[4],
                                         const unsigned b[2]) {
    asm volatile(
        "mma.sync.aligned.m16n8k8.row.col.f32.tf32.tf32.f32 "
        "{%0,%1,%2,%3},{%4,%5,%6,%7},{%8,%9},{%0,%1,%2,%3};\n"
        : "+f"(c[0]), "+f"(c[1]), "+f"(c[2]), "+f"(c[3])
        : "r"(a[0]), "r"(a[1]), "r"(a[2]), "r"(a[3]), "r"(b[0]), "r"(b[1]));
}

// ===========================================================================
// K_round: elementwise tf32-rne rounding, 4 float4 per thread (MLP=4)
// ===========================================================================
__global__ void k_round4(const float* __restrict__ src, float* __restrict__ dst,
                         int n4) {
    int base = blockIdx.x * blockDim.x * 4 + threadIdx.x;
    float4 v[4];
    #pragma unroll
    for (int q = 0; q < 4; q++) {
        int i = base + q * blockDim.x;
        if (i < n4) v[q] = ((const float4*)src)[i];
    }
    #pragma unroll
    for (int q = 0; q < 4; q++) {
        int i = base + q * blockDim.x;
        if (i < n4) {
            float4 t = v[q];
            t.x = ftf32(t.x); t.y = ftf32(t.y); t.z = ftf32(t.z); t.w = ftf32(t.w);
            ((float4*)dst)[i] = t;
        }
    }
}

// ===========================================================================
// K1: U = gather(W_e, X) @ W_xh + b_h  via legacy mma.sync tf32
// ===========================================================================
#define AS_STRIDE 36
#define BS_STRIDE 132
#define AS_BUF (128 * AS_STRIDE)
#define BS_BUF (32 * BS_STRIDE)
#define K1_SMEM ((2 * AS_BUF + 2 * BS_BUF) * 4 + 512)

__global__ void k_embed_mma(const int* __restrict__ X,
                            const float* __restrict__ We,
                            const float* __restrict__ Wxh,
                            const float* __restrict__ bh) {
    extern __shared__ float sm[];
    float* As = sm;
    float* Bs = sm + 2 * AS_BUF;
    int*   sIdx = (int*)(sm + 2 * AS_BUF + 2 * BS_BUF);

    const int tid  = threadIdx.x;
    const int lane = tid & 31, warp = tid >> 5;
    const int gid  = lane >> 2, tig = lane & 3;
    const int wm = (warp >> 2) * 64;
    const int wn = (warp & 3) * 32;
    const int m0 = blockIdx.y * 128;
    const int n0 = blockIdx.x * 128;

    if (tid < 128) sIdx[tid] = X[m0 + tid];
    __syncthreads();

    float c[4][4][4];
    #pragma unroll
    for (int mi = 0; mi < 4; mi++)
        #pragma unroll
        for (int ni = 0; ni < 4; ni++)
            #pragma unroll
            for (int r = 0; r < 4; r++) c[mi][ni][r] = 0.f;

    float4 pa[4], pb[4];
    auto ldA = [&](int k0) {
        #pragma unroll
        for (int q = 0; q < 4; q++) {
            int id = tid + q * 256, r = id >> 3, c4 = id & 7;
            pa[q] = *(const float4*)&We[(size_t)sIdx[r] * EMB + k0 + c4 * 4];
        }
    };
    auto ldB = [&](int k0) {
        #pragma unroll
        for (int q = 0; q < 4; q++) {
            int id = tid + q * 256, r = id >> 5, c4 = id & 31;
            pb[q] = *(const float4*)&Wxh[(size_t)(k0 + r) * HID + n0 + c4 * 4];
        }
    };
    auto stA = [&](float* Ab) {
        #pragma unroll
        for (int q = 0; q < 4; q++) {
            int id = tid + q * 256, r = id >> 3, c4 = id & 7;
            float4 v = pa[q];
            v.x = ftf32(v.x); v.y = ftf32(v.y); v.z = ftf32(v.z); v.w = ftf32(v.w);
            *(float4*)&Ab[r * AS_STRIDE + c4 * 4] = v;
        }
    };
    auto stB = [&](float* Bb) {
        #pragma unroll
        for (int q = 0; q < 4; q++) {
            int id = tid + q * 256, r = id >> 5, c4 = id & 31;
            float4 v = pb[q];
            v.x = ftf32(v.x); v.y = ftf32(v.y); v.z = ftf32(v.z); v.w = ftf32(v.w);
            *(float4*)&Bb[r * BS_STRIDE + c4 * 4] = v;
        }
    };

    ldA(0); ldB(0);
    stA(As); stB(Bs);
    __syncthreads();

    int buf = 0;
    for (int kt = 0; kt < 32; kt++) {
        if (kt < 31) { ldA((kt + 1) * 32); ldB((kt + 1) * 32); }
        const float* Ab = As + buf * AS_BUF;
        const float* Bb = Bs + buf * BS_BUF;
        #pragma unroll
        for (int kk = 0; kk < 32; kk += 8) {
            unsigned af[4][4], bf[4][2];
            #pragma unroll
            for (int mi = 0; mi < 4; mi++) {
                int mr = wm + mi * 16 + gid;
                af[mi][0] = __float_as_uint(Ab[mr * AS_STRIDE + kk + tig]);
                af[mi][1] = __float_as_uint(Ab[(mr + 8) * AS_STRIDE + kk + tig]);
                af[mi][2] = __float_as_uint(Ab[mr * AS_STRIDE + kk + tig + 4]);
                af[mi][3] = __float_as_uint(Ab[(mr + 8) * AS_STRIDE + kk + tig + 4]);
            }
            #pragma unroll
            for (int ni = 0; ni < 4; ni++) {
                int nc = wn + ni * 8 + gid;
                bf[ni][0] = __float_as_uint(Bb[(kk + tig) * BS_STRIDE + nc]);
                bf[ni][1] = __float_as_uint(Bb[(kk + tig + 4) * BS_STRIDE + nc]);
            }
            #pragma unroll
            for (int mi = 0; mi < 4; mi++)
                #pragma unroll
                for (int ni = 0; ni < 4; ni++)
                    mma_tf32(c[mi][ni], af[mi], bf[ni]);
        }
        if (kt < 31) { stA(As + (buf ^ 1) * AS_BUF); stB(Bs + (buf ^ 1) * BS_BUF); }
        __syncthreads();
        buf ^= 1;
    }

    #pragma unroll
    for (int mi = 0; mi < 4; mi++) {
        int mr = m0 + wm + mi * 16 + gid;
        #pragma unroll
        for (int ni = 0; ni < 4; ni++) {
            int nc = n0 + wn + ni * 8 + tig * 2;
            float b0 = bh[nc], b1 = bh[nc + 1];
            float2 v0 = make_float2(c[mi][ni][0] + b0, c[mi][ni][1] + b1);
            float2 v1 = make_float2(c[mi][ni][2] + b0, c[mi][ni][3] + b1);
            *(float2*)&g_U[(size_t)mr * HID + nc]       = v0;
            *(float2*)&g_U[(size_t)(mr + 8) * HID + nc] = v1;
        }
    }
}

// ===========================================================================
// K2 (persistent, tensor-core recurrence) — emits fp32 h and tf32 h
// ===========================================================================
#define NCTA2 64
#define JPC2  16
#define HSTR  1028
#define RNN2_SMEM ((BATCH * HSTR + 16 * 256) * 4)

__global__ void __launch_bounds__(512, 1) k_rnn_tc(const float* __restrict__ Whh) {
    extern __shared__ float sm[];
    float* hsm = sm;
    float* red = sm + BATCH * HSTR;

    const int tid  = threadIdx.x;
    const int lane = tid & 31, warp = tid >> 5;
    const int gid  = lane >> 2, tig = lane & 3;
    const int j0   = blockIdx.x * JPC2;
    const int kw   = warp * 64;

    unsigned bf[2][8][2];
    #pragma unroll
    for (int s = 0; s < 2; s++)
        #pragma unroll
        for (int q = 0; q < 8; q++) {
            int k = kw + q * 8 + tig;
            int j = j0 + s * 8 + gid;
            bf[s][q][0] = ftf32u(Whh[(size_t)k * HID + j]);
            bf[s][q][1] = ftf32u(Whh[(size_t)(k + 4) * HID + j]);
        }

    for (int t = 0; t < T_STEPS; t++) {
        float c0[4] = {0.f, 0.f, 0.f, 0.f};
        float c1[4] = {0.f, 0.f, 0.f, 0.f};

        if (t > 0) {
            const float* hp = g_Hs + (size_t)(t - 1) * BATCH * HID;
            #pragma unroll
            for (int q = 0; q < 8; q++) {
                int f4 = tid + q * 512;
                int row = f4 >> 8, c4 = f4 & 255;
                float4 v = __ldcg((const float4*)&hp[(size_t)row * HID + c4 * 4]);
                *(float4*)&hsm[row * HSTR + c4 * 4] = v;
            }
            __syncthreads();

            #pragma unroll
            for (int q = 0; q < 8; q++) {
                const int k0 = kw + q * 8;
                unsigned af[4];
                af[0] = ftf32u(hsm[gid * HSTR + k0 + tig]);
                af[1] = ftf32u(hsm[(gid + 8) * HSTR + k0 + tig]);
                af[2] = ftf32u(hsm[gid * HSTR + k0 + tig + 4]);
                af[3] = ftf32u(hsm[(gid + 8) * HSTR + k0 + tig + 4]);
                mma_tf32(c0, af, bf[0][q]);
                mma_tf32(c1, af, bf[1][q]);
            }
        }

        {
            float* rw = red + warp * 256;
            rw[gid * 16 + tig * 2]           = c0[0];
            rw[gid * 16 + tig * 2 + 1]       = c0[1];
            rw[(gid + 8) * 16 + tig * 2]     = c0[2];
            rw[(gid + 8) * 16 + tig * 2 + 1] = c0[3];
            rw[gid * 16 + 8 + tig * 2]           = c1[0];
            rw[gid * 16 + 8 + tig * 2 + 1]       = c1[1];
            rw[(gid + 8) * 16 + 8 + tig * 2]     = c1[2];
            rw[(gid + 8) * 16 + 8 + tig * 2 + 1] = c1[3];
        }
        __syncthreads();

        if (tid < 256) {
            const int b = tid >> 4, n = tid & 15;
            float s = 0.f;
            if (t > 0) {
                #pragma unroll
                for (int w = 0; w < 16; w++)
                    s += red[w * 256 + b * 16 + n];
            }
            const size_t m = (size_t)t * BATCH + b;
            float val = tanhf(g_U[m * HID + j0 + n] + s);
            g_Hs[m * HID + j0 + n]   = val;
            g_Hs32[m * HID + j0 + n] = ftf32(val);
        }
        __threadfence();
        __syncthreads();

        if (t < T_STEPS - 1) {
            if (tid == 0) {
                atomicAdd(&g_gen, 1u);
                const unsigned target = (unsigned)NCTA2 * (t + 1);
                while (*(volatile unsigned*)&g_gen < target) __nanosleep(32);
                __threadfence();
            }
            __syncthreads();
        }
    }
}

// ===========================================================================
// K3: logits = Hs32 @ Whq32 + b_q   (legacy mma tf32)
//     256 threads, CTA 128x256, warp tile 64x64, BK=32, 3-stage cp.async
//     -> 32 barriers total (half of round 12), 128 mma/warp per stage
// ===========================================================================
#define BM3 128
#define BN3 256
#define BK3 32
#define A3S 36                               // A row stride (floats), conflict-free
#define B3S 264                              // B row stride (floats), conflict-free
#define A3_BYTES (BM3 * A3S * 4)             // 18432
#define B3_BYTES (BK3 * B3S * 4)             // 33792
#define STG3 (A3_BYTES + B3_BYTES)           // 52224
#define K3_SMEM (3 * STG3)                   // 156672

__global__ void __launch_bounds__(256, 1)
k_out_gemm4(const float* __restrict__ bq, float* __restrict__ out) {
    extern __shared__ char smc[];
    const uint32_t sb = smem_u32(smc);

    const int tid  = threadIdx.x;
    const int lane = tid & 31, warp = tid >> 5;
    const int gid  = lane >> 2, tig = lane & 3;
    const int wm = (warp & 1) * 64;       // 2 warps along M
    const int wn = (warp >> 1) * 64;      // 4 warps along N
    const int m0 = blockIdx.x * BM3;      // m fastest -> B tile L2 reuse
    const int n0 = blockIdx.y * BN3;

    auto issue = [&](int kt) {
        const int s = kt % 3;
        const uint32_t ab = sb + s * STG3;
        const uint32_t bb = ab + A3_BYTES;
        const int k0 = kt * BK3;
        #pragma unroll
        for (int q = 0; q < 4; q++) {                 // A: 1024 16B chunks
            int id = tid + q * 256;
            int m = id >> 3, kq = id & 7;
            cp16(ab + m * (A3S * 4) + kq * 16,
                 &g_Hs32[(size_t)(m0 + m) * HID + k0 + kq * 4]);
        }
        #pragma unroll
        for (int q = 0; q < 8; q++) {                 // B: 2048 16B chunks
            int id = tid + q * 256;
            int k = id >> 6, n4 = id & 63;
            cp16(bb + k * (B3S * 4) + n4 * 16,
                 &g_Whq32[(size_t)(k0 + k) * VOCAB + n0 + n4 * 4]);
        }
        CP_COMMIT();
    };

    float c[4][8][4];
    #pragma unroll
    for (int mi = 0; mi < 4; mi++)
        #pragma unroll
        for (int ni = 0; ni < 8; ni++)
            #pragma unroll
            for (int r = 0; r < 4; r++) c[mi][ni][r] = 0.f;

    issue(0); issue(1); issue(2);

    for (int kt = 0; kt < 32; kt++) {
        CP_WAIT2();            // stage kt's copies complete
        __syncthreads();       // visible to all warps

        const int s = kt % 3;
        const float* As = (const float*)(smc + s * STG3);
        const float* Bs = (const float*)(smc + s * STG3 + A3_BYTES);

        #pragma unroll
        for (int kk = 0; kk < BK3; kk += 8) {
            unsigned af[4][4], bf[8][2];
            #pragma unroll
            for (int mi = 0; mi < 4; mi++) {
                int mr = wm + mi * 16 + gid;
                af[mi][0] = __float_as_uint(As[mr * A3S + kk + tig]);
                af[mi][1] = __float_as_uint(As[(mr + 8) * A3S + kk + tig]);
                af[mi][2] = __float_as_uint(As[mr * A3S + kk + tig + 4]);
                af[mi][3] = __float_as_uint(As[(mr + 8) * A3S + kk + tig + 4]);
            }
            #pragma unroll
            for (int ni = 0; ni < 8; ni++) {
                int nc = wn + ni * 8 + gid;
                bf[ni][0] = __float_as_uint(Bs[(kk + tig) * B3S + nc]);
                bf[ni][1] = __float_as_uint(Bs[(kk + tig + 4) * B3S + nc]);
            }
            #pragma unroll
            for (int mi = 0; mi < 4; mi++)
                #pragma unroll
                for (int ni = 0; ni < 8; ni++)
                    mma_tf32(c[mi][ni], af[mi], bf[ni]);
        }

        __syncthreads();       // all reads of stage kt done
        if (kt + 3 < 32) issue(kt + 3);   // refill this buffer
    }
    CP_WAIT0();

    #pragma unroll
    for (int mi = 0; mi < 4; mi++) {
        int mr = m0 + wm + mi * 16 + gid;
        #pragma unroll
        for (int ni = 0; ni < 8; ni++) {
            int nc = n0 + wn + ni * 8 + tig * 2;
            float b0 = bq[nc], b1 = bq[nc + 1];
            float2 v0 = make_float2(c[mi][ni][0] + b0, c[mi][ni][1] + b1);
            float2 v1 = make_float2(c[mi][ni][2] + b0, c[mi][ni][3] + b1);
            *(float2*)&out[(size_t)mr * VOCAB + nc]       = v0;
            *(float2*)&out[(size_t)(mr + 8) * VOCAB + nc] = v1;
        }
    }
}

// ===========================================================================
extern "C" void kernel_launch(void* const* d_in, const int* in_sizes, int n_in,
                              void* d_out, int out_size) {
    const int*   X   = (const int*)  d_in[0];
    const float* We  = (const float*)d_in[1];
    const float* Wxh = (const float*)d_in[2];
    const float* Whh = (const float*)d_in[3];
    const float* bh  = (const float*)d_in[4];
    const float* Whq = (const float*)d_in[5];
    const float* bq  = (const float*)d_in[6];
    float*       out = (float*)d_out;

    cudaFuncSetAttribute(k_embed_mma,
                         cudaFuncAttributeMaxDynamicSharedMemorySize, K1_SMEM);
    cudaFuncSetAttribute(k_rnn_tc,
                         cudaFuncAttributeMaxDynamicSharedMemorySize, RNN2_SMEM);
    cudaFuncSetAttribute(k_out_gemm4,
                         cudaFuncAttributeMaxDynamicSharedMemorySize, K3_SMEM);

    void *gen_ptr = nullptr, *whq32 = nullptr;
    cudaGetSymbolAddress(&gen_ptr, g_gen);
    cudaGetSymbolAddress(&whq32, g_Whq32);

    cudaMemsetAsync(gen_ptr, 0, sizeof(unsigned), 0);

    {
        int n4 = HID * VOCAB / 4;
        int blocks = (n4 + 1023) / 1024;
        k_round4<<<blocks, 256>>>(Whq, (float*)whq32, n4);
    }
    k_embed_mma<<<dim3(HID / 128, M_TOTAL / 128), 256, K1_SMEM>>>(X, We, Wxh, bh);
    k_rnn_tc<<<NCTA2, 512, RNN2_SMEM>>>(Whh);
    k_out_gemm4<<<dim3(M_TOTAL / BM3, VOCAB / BN3), 256, K3_SMEM>>>(bq, out);
}

// round 15
// speedup vs baseline: 1.1576x; 1.0432x over previous
#include <cuda_runtime.h>
#include <cstdint>

#define T_STEPS 256
#define BATCH   16
#define EMB     1024
#define HID     1024
#define VOCAB   32000
#define M_TOTAL (T_STEPS * BATCH)   // 4096

// Scratch (static device globals — allocation-free per harness rules)
__device__ float    g_U    [M_TOTAL * HID];   // 16 MB
__device__ float    g_Hs   [M_TOTAL * HID];   // 16 MB (fp32 hidden states)
__device__ float    g_Hs32 [M_TOTAL * HID];   // 16 MB (tf32-rounded copy)
__device__ float    g_Whq32[HID * VOCAB];     // 128 MB (tf32-rounded W_hq)
__device__ unsigned g_gen;                    // grid-barrier counter

// ===========================================================================
// helpers
// ===========================================================================
__device__ __forceinline__ float ftf32(float x) {
    unsigned u;
    asm("cvt.rna.tf32.f32 %0, %1;" : "=r"(u) : "f"(x));
    return __uint_as_float(u);
}
__device__ __forceinline__ unsigned ftf32u(float x) {
    unsigned u;
    asm("cvt.rna.tf32.f32 %0, %1;" : "=r"(u) : "f"(x));
    return u;
}
__device__ __forceinline__ uint32_t smem_u32(const void* p) {
    uint32_t a;
    asm("{ .reg .u64 t; cvta.to.shared.u64 t, %1; cvt.u32.u64 %0, t; }"
        : "=r"(a) : "l"(p));
    return a;
}
__device__ __forceinline__ void cp16(uint32_t dst, const void* src) {
    asm volatile("cp.async.cg.shared.global [%0], [%1], 16;"
                 :: "r"(dst), "l"(src) : "memory");
}
#define CP_COMMIT() asm volatile("cp.async.commit_group;" ::: "memory")
#define CP_WAIT2()  asm volatile("cp.async.wait_group 2;" ::: "memory")
#define CP_WAIT0()  asm volatile("cp.async.wait_group 0;" ::: "memory")

__device__ __forceinline__ void mma_tf32(float c[4], const unsigned a[4],
                                         const unsigned b[2]) {
    asm volatile(
        "mma.sync.aligned.m16n8k8.row.col.f32.tf32.tf32.f32 "
        "{%0,%1,%2,%3},{%4,%5,%6,%7},{%8,%9},{%0,%1,%2,%3};\n"
        : "+f"(c[0]), "+f"(c[1]), "+f"(c[2]), "+f"(c[3])
        : "r"(a[0]), "r"(a[1]), "r"(a[2]), "r"(a[3]), "r"(b[0]), "r"(b[1]));
}

// ===========================================================================
// K_round: elementwise tf32-rne rounding, 4 float4 per thread (MLP=4)
// ===========================================================================
__global__ void k_round4(const float* __restrict__ src, float* __restrict__ dst,
                         int n4) {
    int base = blockIdx.x * blockDim.x * 4 + threadIdx.x;
    float4 v[4];
    #pragma unroll
    for (int q = 0; q < 4; q++) {
        int i = base + q * blockDim.x;
        if (i < n4) v[q] = ((const float4*)src)[i];
    }
    #pragma unroll
    for (int q = 0; q < 4; q++) {
        int i = base + q * blockDim.x;
        if (i < n4) {
            float4 t = v[q];
            t.x = ftf32(t.x); t.y = ftf32(t.y); t.z = ftf32(t.z); t.w = ftf32(t.w);
            ((float4*)dst)[i] = t;
        }
    }
}

// ===========================================================================
// K1: U = gather(W_e, X) @ W_xh + b_h  via legacy mma.sync tf32
// ===========================================================================
#define AS_STRIDE 36
#define BS_STRIDE 132
#define AS_BUF (128 * AS_STRIDE)
#define BS_BUF (32 * BS_STRIDE)
#define K1_SMEM ((2 * AS_BUF + 2 * BS_BUF) * 4 + 512)

__global__ void k_embed_mma(const int* __restrict__ X,
                            const float* __restrict__ We,
                            const float* __restrict__ Wxh,
                            const float* __restrict__ bh) {
    extern __shared__ float sm[];
    float* As = sm;
    float* Bs = sm + 2 * AS_BUF;
    int*   sIdx = (int*)(sm + 2 * AS_BUF + 2 * BS_BUF);

    const int tid  = threadIdx.x;
    const int lane = tid & 31, warp = tid >> 5;
    const int gid  = lane >> 2, tig = lane & 3;
    const int wm = (warp >> 2) * 64;
    const int wn = (warp & 3) * 32;
    const int m0 = blockIdx.y * 128;
    const int n0 = blockIdx.x * 128;

    if (tid < 128) sIdx[tid] = X[m0 + tid];
    __syncthreads();

    float c[4][4][4];
    #pragma unroll
    for (int mi = 0; mi < 4; mi++)
        #pragma unroll
        for (int ni = 0; ni < 4; ni++)
            #pragma unroll
            for (int r = 0; r < 4; r++) c[mi][ni][r] = 0.f;

    float4 pa[4], pb[4];
    auto ldA = [&](int k0) {
        #pragma unroll
        for (int q = 0; q < 4; q++) {
            int id = tid + q * 256, r = id >> 3, c4 = id & 7;
            pa[q] = *(const float4*)&We[(size_t)sIdx[r] * EMB + k0 + c4 * 4];
        }
    };
    auto ldB = [&](int k0) {
        #pragma unroll
        for (int q = 0; q < 4; q++) {
            int id = tid + q * 256, r = id >> 5, c4 = id & 31;
            pb[q] = *(const float4*)&Wxh[(size_t)(k0 + r) * HID + n0 + c4 * 4];
        }
    };
    auto stA = [&](float* Ab) {
        #pragma unroll
        for (int q = 0; q < 4; q++) {
            int id = tid + q * 256, r = id >> 3, c4 = id & 7;
            float4 v = pa[q];
            v.x = ftf32(v.x); v.y = ftf32(v.y); v.z = ftf32(v.z); v.w = ftf32(v.w);
            *(float4*)&Ab[r * AS_STRIDE + c4 * 4] = v;
        }
    };
    auto stB = [&](float* Bb) {
        #pragma unroll
        for (int q = 0; q < 4; q++) {
            int id = tid + q * 256, r = id >> 5, c4 = id & 31;
            float4 v = pb[q];
            v.x = ftf32(v.x); v.y = ftf32(v.y); v.z = ftf32(v.z); v.w = ftf32(v.w);
            *(float4*)&Bb[r * BS_STRIDE + c4 * 4] = v;
        }
    };

    ldA(0); ldB(0);
    stA(As); stB(Bs);
    __syncthreads();

    int buf = 0;
    for (int kt = 0; kt < 32; kt++) {
        if (kt < 31) { ldA((kt + 1) * 32); ldB((kt + 1) * 32); }
        const float* Ab = As + buf * AS_BUF;
        const float* Bb = Bs + buf * BS_BUF;
        #pragma unroll
        for (int kk = 0; kk < 32; kk += 8) {
            unsigned af[4][4], bf[4][2];
            #pragma unroll
            for (int mi = 0; mi < 4; mi++) {
                int mr = wm + mi * 16 + gid;
                af[mi][0] = __float_as_uint(Ab[mr * AS_STRIDE + kk + tig]);
                af[mi][1] = __float_as_uint(Ab[(mr + 8) * AS_STRIDE + kk + tig]);
                af[mi][2] = __float_as_uint(Ab[mr * AS_STRIDE + kk + tig + 4]);
                af[mi][3] = __float_as_uint(Ab[(mr + 8) * AS_STRIDE + kk + tig + 4]);
            }
            #pragma unroll
            for (int ni = 0; ni < 4; ni++) {
                int nc = wn + ni * 8 + gid;
                bf[ni][0] = __float_as_uint(Bb[(kk + tig) * BS_STRIDE + nc]);
                bf[ni][1] = __float_as_uint(Bb[(kk + tig + 4) * BS_STRIDE + nc]);
            }
            #pragma unroll
            for (int mi = 0; mi < 4; mi++)
                #pragma unroll
                for (int ni = 0; ni < 4; ni++)
                    mma_tf32(c[mi][ni], af[mi], bf[ni]);
        }
        if (kt < 31) { stA(As + (buf ^ 1) * AS_BUF); stB(Bs + (buf ^ 1) * BS_BUF); }
        __syncthreads();
        buf ^= 1;
    }

    #pragma unroll
    for (int mi = 0; mi < 4; mi++) {
        int mr = m0 + wm + mi * 16 + gid;
        #pragma unroll
        for (int ni = 0; ni < 4; ni++) {
            int nc = n0 + wn + ni * 8 + tig * 2;
            float b0 = bh[nc], b1 = bh[nc + 1];
            float2 v0 = make_float2(c[mi][ni][0] + b0, c[mi][ni][1] + b1);
            float2 v1 = make_float2(c[mi][ni][2] + b0, c[mi][ni][3] + b1);
            *(float2*)&g_U[(size_t)mr * HID + nc]       = v0;
            *(float2*)&g_U[(size_t)(mr + 8) * HID + nc] = v1;
        }
    }
}

// ===========================================================================
// K2 (persistent, tensor-core recurrence) — emits fp32 h and tf32 h
// ===========================================================================
#define NCTA2 64
#define JPC2  16
#define HSTR  1028
#define RNN2_SMEM ((BATCH * HSTR + 16 * 256) * 4)

__global__ void __launch_bounds__(512, 1) k_rnn_tc(const float* __restrict__ Whh) {
    extern __shared__ float sm[];
    float* hsm = sm;
    float* red = sm + BATCH * HSTR;

    const int tid  = threadIdx.x;
    const int lane = tid & 31, warp = tid >> 5;
    const int gid  = lane >> 2, tig = lane & 3;
    const int j0   = blockIdx.x * JPC2;
    const int kw   = warp * 64;

    unsigned bf[2][8][2];
    #pragma unroll
    for (int s = 0; s < 2; s++)
        #pragma unroll
        for (int q = 0; q < 8; q++) {
            int k = kw + q * 8 + tig;
            int j = j0 + s * 8 + gid;
            bf[s][q][0] = ftf32u(Whh[(size_t)k * HID + j]);
            bf[s][q][1] = ftf32u(Whh[(size_t)(k + 4) * HID + j]);
        }

    for (int t = 0; t < T_STEPS; t++) {
        float c0[4] = {0.f, 0.f, 0.f, 0.f};
        float c1[4] = {0.f, 0.f, 0.f, 0.f};

        if (t > 0) {
            const float* hp = g_Hs + (size_t)(t - 1) * BATCH * HID;
            #pragma unroll
            for (int q = 0; q < 8; q++) {
                int f4 = tid + q * 512;
                int row = f4 >> 8, c4 = f4 & 255;
                float4 v = __ldcg((const float4*)&hp[(size_t)row * HID + c4 * 4]);
                *(float4*)&hsm[row * HSTR + c4 * 4] = v;
            }
            __syncthreads();

            #pragma unroll
            for (int q = 0; q < 8; q++) {
                const int k0 = kw + q * 8;
                unsigned af[4];
                af[0] = ftf32u(hsm[gid * HSTR + k0 + tig]);
                af[1] = ftf32u(hsm[(gid + 8) * HSTR + k0 + tig]);
                af[2] = ftf32u(hsm[gid * HSTR + k0 + tig + 4]);
                af[3] = ftf32u(hsm[(gid + 8) * HSTR + k0 + tig + 4]);
                mma_tf32(c0, af, bf[0][q]);
                mma_tf32(c1, af, bf[1][q]);
            }
        }

        {
            float* rw = red + warp * 256;
            rw[gid * 16 + tig * 2]           = c0[0];
            rw[gid * 16 + tig * 2 + 1]       = c0[1];
            rw[(gid + 8) * 16 + tig * 2]     = c0[2];
            rw[(gid + 8) * 16 + tig * 2 + 1] = c0[3];
            rw[gid * 16 + 8 + tig * 2]           = c1[0];
            rw[gid * 16 + 8 + tig * 2 + 1]       = c1[1];
            rw[(gid + 8) * 16 + 8 + tig * 2]     = c1[2];
            rw[(gid + 8) * 16 + 8 + tig * 2 + 1] = c1[3];
        }
        __syncthreads();

        if (tid < 256) {
            const int b = tid >> 4, n = tid & 15;
            float s = 0.f;
            if (t > 0) {
                #pragma unroll
                for (int w = 0; w < 16; w++)
                    s += red[w * 256 + b * 16 + n];
            }
            const size_t m = (size_t)t * BATCH + b;
            float val = tanhf(g_U[m * HID + j0 + n] + s);
            g_Hs[m * HID + j0 + n]   = val;
            g_Hs32[m * HID + j0 + n] = ftf32(val);
        }
        __threadfence();
        __syncthreads();

        if (t < T_STEPS - 1) {
            if (tid == 0) {
                atomicAdd(&g_gen, 1u);
                const unsigned target = (unsigned)NCTA2 * (t + 1);
                while (*(volatile unsigned*)&g_gen < target) __nanosleep(32);
                __threadfence();
            }
            __syncthreads();
        }
    }
}

// ===========================================================================
// K3: logits = Hs32 @ Whq32 + b_q   (legacy mma tf32)
//     128 threads/CTA, CTA tile 128x128, 4 warps of 64x64, BK=32, 3-stage
//     -> 2 CTAs/SM: independent barrier domains cover each other's stalls
// ===========================================================================
#define BM3 128
#define BN3 128
#define BK3 32
#define A3S 36                               // A row stride (floats), conflict-free
#define B3S 136                              // B row stride: 136%32=8 -> conflict-free
#define A3_BYTES (BM3 * A3S * 4)             // 18432
#define B3_BYTES (BK3 * B3S * 4)             // 17408
#define STG3 (A3_BYTES + B3_BYTES)           // 35840
#define K3_SMEM (3 * STG3)                   // 107520  (2 CTAs/SM)

__global__ void __launch_bounds__(128)
k_out_gemm5(const float* __restrict__ bq, float* __restrict__ out) {
    extern __shared__ char smc[];
    const uint32_t sb = smem_u32(smc);

    const int tid  = threadIdx.x;
    const int lane = tid & 31, warp = tid >> 5;   // 4 warps
    const int gid  = lane >> 2, tig = lane & 3;
    const int wm = (warp & 1) * 64;       // 2 warps along M
    const int wn = (warp >> 1) * 64;      // 2 warps along N
    const int m0 = blockIdx.x * BM3;      // m fastest -> B tile L2 reuse
    const int n0 = blockIdx.y * BN3;

    auto issue = [&](int kt) {
        const int s = kt % 3;
        const uint32_t ab = sb + s * STG3;
        const uint32_t bb = ab + A3_BYTES;
        const int k0 = kt * BK3;
        #pragma unroll
        for (int q = 0; q < 8; q++) {                 // A: 1024 16B chunks
            int id = tid + q * 128;
            int m = id >> 3, kq = id & 7;
            cp16(ab + m * (A3S * 4) + kq * 16,
                 &g_Hs32[(size_t)(m0 + m) * HID + k0 + kq * 4]);
        }
        #pragma unroll
        for (int q = 0; q < 8; q++) {                 // B: 1024 16B chunks
            int id = tid + q * 128;
            int k = id >> 5, n4 = id & 31;
            cp16(bb + k * (B3S * 4) + n4 * 16,
                 &g_Whq32[(size_t)(k0 + k) * VOCAB + n0 + n4 * 4]);
        }
        CP_COMMIT();
    };

    float c[4][8][4];
    #pragma unroll
    for (int mi = 0; mi < 4; mi++)
        #pragma unroll
        for (int ni = 0; ni < 8; ni++)
            #pragma unroll
            for (int r = 0; r < 4; r++) c[mi][ni][r] = 0.f;

    issue(0); issue(1); issue(2);

    for (int kt = 0; kt < 32; kt++) {
        CP_WAIT2();            // stage kt's copies complete
        __syncthreads();       // visible to all warps

        const int s = kt % 3;
        const float* As = (const float*)(smc + s * STG3);
        const float* Bs = (const float*)(smc + s * STG3 + A3_BYTES);

        #pragma unroll
        for (int kk = 0; kk < BK3; kk += 8) {
            unsigned af[4][4], bf[8][2];
            #pragma unroll
            for (int mi = 0; mi < 4; mi++) {
                int mr = wm + mi * 16 + gid;
                af[mi][0] = __float_as_uint(As[mr * A3S + kk + tig]);
                af[mi][1] = __float_as_uint(As[(mr + 8) * A3S + kk + tig]);
                af[mi][2] = __float_as_uint(As[mr * A3S + kk + tig + 4]);
                af[mi][3] = __float_as_uint(As[(mr + 8) * A3S + kk + tig + 4]);
            }
            #pragma unroll
            for (int ni = 0; ni < 8; ni++) {
                int nc = wn + ni * 8 + gid;
                bf[ni][0] = __float_as_uint(Bs[(kk + tig) * B3S + nc]);
                bf[ni][1] = __float_as_uint(Bs[(kk + tig + 4) * B3S + nc]);
            }
            #pragma unroll
            for (int mi = 0; mi < 4; mi++)
                #pragma unroll
                for (int ni = 0; ni < 8; ni++)
                    mma_tf32(c[mi][ni], af[mi], bf[ni]);
        }

        __syncthreads();       // all reads of stage kt done
        if (kt + 3 < 32) issue(kt + 3);   // refill this buffer
    }
    CP_WAIT0();

    #pragma unroll
    for (int mi = 0; mi < 4; mi++) {
        int mr = m0 + wm + mi * 16 + gid;
        #pragma unroll
        for (int ni = 0; ni < 8; ni++) {
            int nc = n0 + wn + ni * 8 + tig * 2;
            float b0 = bq[nc], b1 = bq[nc + 1];
            float2 v0 = make_float2(c[mi][ni][0] + b0, c[mi][ni][1] + b1);
            float2 v1 = make_float2(c[mi][ni][2] + b0, c[mi][ni][3] + b1);
            *(float2*)&out[(size_t)mr * VOCAB + nc]       = v0;
            *(float2*)&out[(size_t)(mr + 8) * VOCAB + nc] = v1;
        }
    }
}

// ===========================================================================
extern "C" void kernel_launch(void* const* d_in, const int* in_sizes, int n_in,
                              void* d_out, int out_size) {
    const int*   X   = (const int*)  d_in[0];
    const float* We  = (const float*)d_in[1];
    const float* Wxh = (const float*)d_in[2];
    const float* Whh = (const float*)d_in[3];
    const float* bh  = (const float*)d_in[4];
    const float* Whq = (const float*)d_in[5];
    const float* bq  = (const float*)d_in[6];
    float*       out = (float*)d_out;

    cudaFuncSetAttribute(k_embed_mma,
                         cudaFuncAttributeMaxDynamicSharedMemorySize, K1_SMEM);
    cudaFuncSetAttribute(k_rnn_tc,
                         cudaFuncAttributeMaxDynamicSharedMemorySize, RNN2_SMEM);
    cudaFuncSetAttribute(k_out_gemm5,
                         cudaFuncAttributeMaxDynamicSharedMemorySize, K3_SMEM);

    void *gen_ptr = nullptr, *whq32 = nullptr;
    cudaGetSymbolAddress(&gen_ptr, g_gen);
    cudaGetSymbolAddress(&whq32, g_Whq32);

    cudaMemsetAsync(gen_ptr, 0, sizeof(unsigned), 0);

    {
        int n4 = HID * VOCAB / 4;
        int blocks = (n4 + 1023) / 1024;
        k_round4<<<blocks, 256>>>(Whq, (float*)whq32, n4);
    }
    k_embed_mma<<<dim3(HID / 128, M_TOTAL / 128), 256, K1_SMEM>>>(X, We, Wxh, bh);
    k_rnn_tc<<<NCTA2, 512, RNN2_SMEM>>>(Whh);
    k_out_gemm5<<<dim3(M_TOTAL / BM3, VOCAB / BN3), 128, K3_SMEM>>>(bq, out);
}